// round 1
// baseline (speedup 1.0000x reference)
#include <cuda_runtime.h>

// ---------------------------------------------------------------------------
// VSN (Temporal Fusion Transformer variable-selection) for B=8,T=2048,NV=16,D=256
// Round 1: correct fp32 SIMT baseline.  All GEMM dims divide tile sizes evenly.
// ---------------------------------------------------------------------------

#define BT_TOK 16384L      // B*T
#define NVAR   16
#define DDIM   256
#define DIN    4096        // NV*D

// scratch layout (floats)
#define OFF_H1   0L                    // [BT,256]
#define OFF_H2   4194304L              // [BT,256]
#define OFF_HV1  8388608L              // [NV][BT][256]
#define OFF_HV2  75497472L             // [NV][BT][256]
#define OFF_HV3  142606336L            // [NV][BT][512]
#define OFF_SKIP 276824064L            // [BT,16]
#define SCRATCH_TOTAL 277086208L

__device__ __align__(256) float g_scratch[SCRATCH_TOTAL];

__device__ __forceinline__ const float* rsrc(const float* p, long off) {
    return p ? p : (const float*)(g_scratch + off);
}

// ---------------------------------------------------------------------------
// Tiled GEMM: C[M,N] = act(A[M,K] @ W[K,N] + bias[N]), row-major.
// Tile 64x64, K-step 16, 256 threads, 4x4 microtile. batched via blockIdx.z.
// act: 0 = identity, 1 = ELU
// ---------------------------------------------------------------------------
__global__ __launch_bounds__(256)
void gemm_bias_act(const float* __restrict__ Aext, long aoff, int lda, long long sA,
                   const float* __restrict__ W, long long sW,
                   const float* __restrict__ bias, long long sB,
                   long coff, int ldc, long long sC,
                   int N, int K, int act)
{
    const int v = blockIdx.z;
    const float* A = rsrc(Aext, aoff) + (long long)v * sA;
    const float* Wp = W + (long long)v * sW;
    const float* bp = bias + (long long)v * sB;
    float* C = g_scratch + coff + (long long)v * sC;

    const int m0 = blockIdx.y * 64;
    const int n0 = blockIdx.x * 64;

    __shared__ float As[16][65];   // transposed A tile (k-major), pad 1 (conflict-light)
    __shared__ float Bs[16][64];

    const int tid = threadIdx.x;
    const int tx = tid & 15;          // 0..15 -> 4 cols each
    const int ty = tid >> 4;          // 0..15 -> 4 rows each
    const int ar = tid >> 2;          // A tile row 0..63
    const int ac = (tid & 3) << 2;    // A tile col 0,4,8,12
    const int br = tid >> 4;          // W tile row 0..15
    const int bc = (tid & 15) << 2;   // W tile col

    float acc[4][4];
#pragma unroll
    for (int i = 0; i < 4; i++)
#pragma unroll
        for (int j = 0; j < 4; j++) acc[i][j] = 0.f;

    const float* Aptr = A + (long long)(m0 + ar) * lda + ac;
    const float* Wptr = Wp + (long long)br * N + n0 + bc;

    for (int k0 = 0; k0 < K; k0 += 16) {
        float4 av = *reinterpret_cast<const float4*>(Aptr + k0);
        As[ac + 0][ar] = av.x;
        As[ac + 1][ar] = av.y;
        As[ac + 2][ar] = av.z;
        As[ac + 3][ar] = av.w;
        float4 wv = *reinterpret_cast<const float4*>(Wptr + (long long)k0 * N);
        *reinterpret_cast<float4*>(&Bs[br][bc]) = wv;
        __syncthreads();

#pragma unroll
        for (int kk = 0; kk < 16; kk++) {
            float a[4], b[4];
#pragma unroll
            for (int i = 0; i < 4; i++) a[i] = As[kk][ty * 4 + i];
#pragma unroll
            for (int j = 0; j < 4; j++) b[j] = Bs[kk][tx * 4 + j];
#pragma unroll
            for (int i = 0; i < 4; i++)
#pragma unroll
                for (int j = 0; j < 4; j++) acc[i][j] += a[i] * b[j];
        }
        __syncthreads();
    }

#pragma unroll
    for (int i = 0; i < 4; i++) {
        float* Crow = C + (long long)(m0 + ty * 4 + i) * ldc + n0 + tx * 4;
#pragma unroll
        for (int j = 0; j < 4; j++) {
            float val = acc[i][j] + bp[n0 + tx * 4 + j];
            if (act == 1) val = (val > 0.f) ? val : expm1f(val);
            Crow[j] = val;
        }
    }
}

// ---------------------------------------------------------------------------
// Skip GEMM: skip[BT,16] = flat[BT,4096] @ Wgs[4096,16] + bgs
// Block: 16 tokens x 16 outputs = 256 threads. K staged 64 at a time.
// ---------------------------------------------------------------------------
__global__ __launch_bounds__(256)
void skip_kernel(const float* __restrict__ vars,
                 const float* __restrict__ Wgs,
                 const float* __restrict__ bgs)
{
    __shared__ float As[16][64];
    __shared__ float Ws[64][16];

    const int tid = threadIdx.x;
    const long t0 = (long)blockIdx.x * 16;
    const int o = tid & 15;        // output 0..15
    const int tr = tid >> 4;       // token-in-tile 0..15
    const int awr = tid >> 4;      // A load row
    const int awc = (tid & 15) << 2;
    const int wwr = tid >> 2;      // W load row 0..63
    const int wwc = (tid & 3) << 2;

    float s = 0.f;
    for (int k0 = 0; k0 < DIN; k0 += 64) {
        float4 av = *reinterpret_cast<const float4*>(vars + (t0 + awr) * DIN + k0 + awc);
        *reinterpret_cast<float4*>(&As[awr][awc]) = av;
        float4 wv = *reinterpret_cast<const float4*>(Wgs + (long)(k0 + wwr) * 16 + wwc);
        *reinterpret_cast<float4*>(&Ws[wwr][wwc]) = wv;
        __syncthreads();
#pragma unroll 16
        for (int kk = 0; kk < 64; kk++) s += As[tr][kk] * Ws[kk][o];
        __syncthreads();
    }
    g_scratch[OFF_SKIP + (t0 + tr) * 16 + o] = s + bgs[o];
}

// ---------------------------------------------------------------------------
// Weight logits: per token (warp-level):
//   y[32] = h2[t] @ Wg3 + bg3 ;  r = glu(y) + skip[t] ; LN(gg,bgn) ; softmax
// 8 tokens per 256-thread block (one warp each).
// ---------------------------------------------------------------------------
__global__ __launch_bounds__(256)
void wlogits_kernel(const float* __restrict__ Wg3,
                    const float* __restrict__ bg3,
                    const float* __restrict__ gg,
                    const float* __restrict__ bgn,
                    float* __restrict__ wout)
{
    const int tid = threadIdx.x;
    const int lane = tid & 31;
    const long t = (long)blockIdx.x * 8 + (tid >> 5);

    const float* h2t = (const float*)(g_scratch + OFF_H2) + t * 256;
    float s = bg3[lane];
    for (int k = 0; k < 256; k++) s += h2t[k] * Wg3[k * 32 + lane];

    // GLU: a = y[0:16] (lanes 0..15), b = y[16:32]
    float bhalf = __shfl_down_sync(0xffffffffu, s, 16);
    float r = 0.f;
    if (lane < 16)
        r = s * (1.f / (1.f + expf(-bhalf))) + g_scratch[OFF_SKIP + t * 16 + lane];

    // LayerNorm over 16 lanes (width-16 shuffles keep groups separate)
    float sum = r;
    for (int m = 8; m; m >>= 1) sum += __shfl_xor_sync(0xffffffffu, sum, m, 16);
    float mean = sum * (1.f / 16.f);
    float d = r - mean;
    float vs = d * d;
    for (int m = 8; m; m >>= 1) vs += __shfl_xor_sync(0xffffffffu, vs, m, 16);
    float rstd = rsqrtf(vs * (1.f / 16.f) + 1e-6f);
    float ln = 0.f;
    if (lane < 16) ln = d * rstd * gg[lane] + bgn[lane];

    // softmax over 16 lanes
    float mx = ln;
    for (int m = 8; m; m >>= 1) mx = fmaxf(mx, __shfl_xor_sync(0xffffffffu, mx, m, 16));
    float e = (lane < 16) ? expf(ln - mx) : 0.f;
    float se = e;
    for (int m = 8; m; m >>= 1) se += __shfl_xor_sync(0xffffffffu, se, m, 16);
    if (lane < 16) wout[t * 16 + lane] = e / se;
}

// ---------------------------------------------------------------------------
// enc+combine: per token t, for each v:
//   e = glu(hv3[v,t,:512]) + x[t,v,:] ;  enc = LN(e; gv[v], bvn[v])
//   out[t] += enc * weight[t,v]
// One 256-thread block per token (thread = channel d).
// ---------------------------------------------------------------------------
__global__ __launch_bounds__(256)
void enc_combine_kernel(const float* __restrict__ vars,
                        const float* __restrict__ wout,
                        const float* __restrict__ gv,
                        const float* __restrict__ bvn,
                        float* __restrict__ outp)
{
    const long t = blockIdx.x;
    const int tid = threadIdx.x;
    const int lane = tid & 31, wid = tid >> 5;

    __shared__ float sw[16];
    __shared__ float red[18];
    if (tid < 16) sw[tid] = wout[t * 16 + tid];
    __syncthreads();

    const float* hv3 = (const float*)(g_scratch + OFF_HV3);
    float acc = 0.f;

    for (int v = 0; v < NVAR; v++) {
        long base = ((long)v * BT_TOK + t) * 512;
        float a = hv3[base + tid];
        float b = hv3[base + 256 + tid];
        float x = vars[t * DIN + v * DDIM + tid];
        float e = a * (1.f / (1.f + expf(-b))) + x;

        float s1 = e, s2 = e * e;
        for (int m = 16; m; m >>= 1) {
            s1 += __shfl_xor_sync(0xffffffffu, s1, m);
            s2 += __shfl_xor_sync(0xffffffffu, s2, m);
        }
        if (lane == 0) { red[wid] = s1; red[8 + wid] = s2; }
        __syncthreads();
        if (tid == 0) {
            float t1 = 0.f, t2 = 0.f;
            for (int i = 0; i < 8; i++) { t1 += red[i]; t2 += red[8 + i]; }
            float mean = t1 * (1.f / 256.f);
            float var = t2 * (1.f / 256.f) - mean * mean;
            red[16] = mean;
            red[17] = rsqrtf(var + 1e-6f);
        }
        __syncthreads();
        float mean = red[16], rstd = red[17];
        float encv = (e - mean) * rstd * gv[v * DDIM + tid] + bvn[v * DDIM + tid];
        acc += encv * sw[v];
        __syncthreads();   // protect red[] before next iteration's writes
    }
    outp[t * DDIM + tid] = acc;
}

// ---------------------------------------------------------------------------
extern "C" void kernel_launch(void* const* d_in, const int* in_sizes, int n_in,
                              void* d_out, int out_size)
{
    const float* vars = (const float*)d_in[0];
    const float* Wg1  = (const float*)d_in[1];
    const float* bg1  = (const float*)d_in[2];
    const float* Wg2  = (const float*)d_in[3];
    const float* bg2  = (const float*)d_in[4];
    const float* Wg3  = (const float*)d_in[5];
    const float* bg3  = (const float*)d_in[6];
    const float* Wgs  = (const float*)d_in[7];
    const float* bgs  = (const float*)d_in[8];
    const float* gg   = (const float*)d_in[9];
    const float* bgn  = (const float*)d_in[10];
    const float* Wv1  = (const float*)d_in[11];
    const float* bv1  = (const float*)d_in[12];
    const float* Wv2  = (const float*)d_in[13];
    const float* bv2  = (const float*)d_in[14];
    const float* Wv3  = (const float*)d_in[15];
    const float* bv3  = (const float*)d_in[16];
    const float* gv   = (const float*)d_in[17];
    const float* bvn  = (const float*)d_in[18];

    float* out  = (float*)d_out;                 // [BT, 256]
    float* wout = out + BT_TOK * DDIM;           // [BT, 16]

    const long long S1 = BT_TOK * 256;           // per-variable stride (256-wide bufs)
    const long long S3 = BT_TOK * 512;           // per-variable stride (512-wide buf)

    // 1) h1 = elu(flat @ Wg1 + bg1)        [16384,4096]x[4096,256]
    gemm_bias_act<<<dim3(4, 256, 1), 256>>>(vars, 0, DIN, 0, Wg1, 0, bg1, 0,
                                            OFF_H1, 256, 0, 256, 4096, 1);
    // 2) h2 = h1 @ Wg2 + bg2               [16384,256]x[256,256]
    gemm_bias_act<<<dim3(4, 256, 1), 256>>>(nullptr, OFF_H1, 256, 0, Wg2, 0, bg2, 0,
                                            OFF_H2, 256, 0, 256, 256, 0);
    // 3) skip = flat @ Wgs + bgs
    skip_kernel<<<1024, 256>>>(vars, Wgs, bgs);
    // 4) weight[t] = softmax(LN(glu(h2@Wg3+bg3) + skip))
    wlogits_kernel<<<2048, 256>>>(Wg3, bg3, gg, bgn, wout);
    // 5) hv1 = elu(x_v @ Wv1[v] + bv1[v])  batched over v
    gemm_bias_act<<<dim3(4, 256, 16), 256>>>(vars, 0, DIN, 256, Wv1, 65536, bv1, 256,
                                             OFF_HV1, 256, S1, 256, 256, 1);
    // 6) hv2 = hv1 @ Wv2[v] + bv2[v]
    gemm_bias_act<<<dim3(4, 256, 16), 256>>>(nullptr, OFF_HV1, 256, S1, Wv2, 65536, bv2, 256,
                                             OFF_HV2, 256, S1, 256, 256, 0);
    // 7) hv3 = hv2 @ Wv3[v] + bv3[v]       N=512
    gemm_bias_act<<<dim3(8, 256, 16), 256>>>(nullptr, OFF_HV2, 256, S1, Wv3, 131072, bv3, 512,
                                             OFF_HV3, 512, S3, 512, 256, 0);
    // 8) enc = LN(glu(hv3)+x); out = sum_v enc*weight
    enc_combine_kernel<<<16384, 256>>>(vars, wout, gv, bvn, out);
}

// round 3
// speedup vs baseline: 2.7016x; 2.7016x over previous
#include <cuda_runtime.h>
#include <cuda_fp16.h>
#include <cstdint>

// ---------------------------------------------------------------------------
// VSN on GB300 — Round 3: mma.sync fp16 GEMMs (weights hi/lo split, 2 passes)
// sm_103 non-'a' PTX target => no tcgen05; classic HMMA + cp.async instead.
// B=8,T=2048,NV=16,D=256 -> BT=16384, DIN=4096
// ---------------------------------------------------------------------------

#define BT_TOK 16384L
#define DDIM   256
#define DIN    4096

// ---------------- scratch (bytes) ----------------
#define O_VH    0ULL            // vars fp16          [16384,4096]  128MB
#define O_H1    134217728ULL    // h1 fp16            [16384,256]     8MB
#define O_H2F   142606336ULL    // h2 fp32            [16384,256]    16MB
#define O_V1    159383552ULL    // hv1 fp16  16x[16384,256]         128MB
#define O_V2    293601280ULL    // hv2 fp16  16x[16384,256]         128MB
#define O_V3F   427819008ULL    // hv3 fp32  16x[16384,512]         512MB
#define O_SKIP  964689920ULL    // skip fp32 [16384,16]               1MB
#define O_G1H   965738496ULL
#define O_G1L   967835648ULL
#define O_G2H   969932800ULL
#define O_G2L   970063872ULL
#define O_W1H   970194944ULL
#define O_W1L   972292096ULL
#define O_W2H   974389248ULL
#define O_W2L   976486400ULL
#define O_W3H   978583552ULL
#define O_W3L   982777856ULL
#define G_TOTAL 986972160ULL

__device__ __align__(1024) unsigned char g_buf[G_TOTAL];

// ---------------- helpers ----------------
__device__ __forceinline__ uint32_t smem_u32(const void* p) {
    uint32_t a;
    asm("{ .reg .u64 t; cvta.to.shared.u64 t, %1; cvt.u32.u64 %0, t; }" : "=r"(a) : "l"(p));
    return a;
}
__device__ __forceinline__ void cpasync16(uint32_t dst, const void* src) {
    asm volatile("cp.async.cg.shared.global [%0], [%1], 16;" :: "r"(dst), "l"(src));
}
#define CP_COMMIT() asm volatile("cp.async.commit_group;" ::: "memory")
#define CP_WAIT(n)  asm volatile("cp.async.wait_group %0;" :: "n"(n) : "memory")

__device__ __forceinline__ void ldsm_x4(uint32_t (&r)[4], uint32_t addr) {
    asm volatile("ldmatrix.sync.aligned.m8n8.x4.shared.b16 {%0,%1,%2,%3}, [%4];"
        : "=r"(r[0]), "=r"(r[1]), "=r"(r[2]), "=r"(r[3]) : "r"(addr));
}
__device__ __forceinline__ void mma16816(float (&c)[4], const uint32_t (&a)[4],
                                         uint32_t b0, uint32_t b1) {
    asm volatile("mma.sync.aligned.m16n8k16.row.col.f32.f16.f16.f32 "
        "{%0,%1,%2,%3}, {%4,%5,%6,%7}, {%8,%9}, {%0,%1,%2,%3};"
        : "+f"(c[0]), "+f"(c[1]), "+f"(c[2]), "+f"(c[3])
        : "r"(a[0]), "r"(a[1]), "r"(a[2]), "r"(a[3]), "r"(b0), "r"(b1));
}

// ---------------------------------------------------------------------------
// conversions
// ---------------------------------------------------------------------------
__global__ __launch_bounds__(256)
void conv_split(const float* __restrict__ x, __half* __restrict__ h)
{
    size_t i = ((size_t)blockIdx.x * 256 + threadIdx.x) * 4;
    float4 v = *reinterpret_cast<const float4*>(x + i);
    __half2 a = __floats2half2_rn(v.x, v.y);
    __half2 b = __floats2half2_rn(v.z, v.w);
    *reinterpret_cast<__half2*>(h + i)     = a;
    *reinterpret_cast<__half2*>(h + i + 2) = b;
}

// transpose + hi/lo split: W[K,N] -> WT_hi/lo[N,K] (fp16)
__global__ __launch_bounds__(256)
void conv_wT(const float* __restrict__ W, __half* __restrict__ TH,
             __half* __restrict__ TL, int K, int N)
{
    const size_t vb = (size_t)blockIdx.z * K * N;
    __shared__ float tile[32][33];
    const int k0 = blockIdx.y * 32, n0 = blockIdx.x * 32;
    const int tx = threadIdx.x & 31, ty = threadIdx.x >> 5;  // 32 x 8
#pragma unroll
    for (int i = 0; i < 4; i++)
        tile[ty + i * 8][tx] = W[vb + (size_t)(k0 + ty + i * 8) * N + n0 + tx];
    __syncthreads();
#pragma unroll
    for (int i = 0; i < 4; i++) {
        int n = ty + i * 8;
        float x = tile[tx][n];
        __half h = __float2half_rn(x);
        size_t o = vb + (size_t)(n0 + n) * K + k0 + tx;
        TH[o] = h;
        TL[o] = __float2half_rn(x - __half2float(h));
    }
}

// ---------------------------------------------------------------------------
// fp16 mma.sync GEMM: C[128,128] tile = A[128,K] @ (Bh+Bl)^T, B stored [N,K].
// 8 warps: 2(M) x 4(N); warp tile 64x32; BK=64; 2-stage cp.async pipeline.
// mode: 0 = fp32 out, 1 = ELU + fp16 out, 2 = fp16 out
// ---------------------------------------------------------------------------
#define RS 72                       // smem row stride (elements), 144 bytes
#define TILE_BYTES 18432            // 128 * 72 * 2
#define OFF_A  0
#define OFF_BH 18432
#define OFF_BL 36864
#define ST_SIZE 55296
#define SMEM_TOT 110592

__global__ __launch_bounds__(256, 1)
void mma_gemm(const __half* __restrict__ A, long long aV, int lda,
              const __half* __restrict__ BH, const __half* __restrict__ BL,
              long long bV,
              const float* __restrict__ bias, int biasV,
              float* __restrict__ CF, __half* __restrict__ CH,
              long long cV, int ldc, int K, int mode)
{
    extern __shared__ __align__(1024) unsigned char sm[];
    const uint32_t sb = smem_u32(sm);
    const int tid = threadIdx.x;
    const int lane = tid & 31, wid = tid >> 5;
    const int wm = wid & 1, wn = wid >> 1;
    const int v = blockIdx.z;
    const int m0 = blockIdx.y * 128;
    const int nb = blockIdx.x * 128;

    const __half* Ap  = A  + (size_t)v * aV + (size_t)m0 * lda;
    const __half* Bhp = BH + (size_t)v * bV + (size_t)nb * K;
    const __half* Blp = BL + (size_t)v * bV + (size_t)nb * K;

    const int lr = tid >> 3;            // 0..31 (+ t*32)
    const int lc = (tid & 7) * 8;       // chunk col in elements

    float acc[4][4][4];
#pragma unroll
    for (int i = 0; i < 4; i++)
#pragma unroll
        for (int j = 0; j < 4; j++)
#pragma unroll
            for (int k = 0; k < 4; k++) acc[i][j][k] = 0.f;

    const int nc = K >> 6;

    // ---- stage loader ----
    auto load_stage = [&](int s, int k0) {
        const uint32_t base = sb + s * ST_SIZE;
#pragma unroll
        for (int t = 0; t < 4; t++) {
            const int row = lr + t * 32;
            const uint32_t doff = (uint32_t)(row * RS + lc) * 2;
            cpasync16(base + OFF_A  + doff, Ap  + (size_t)row * lda + k0 + lc);
            cpasync16(base + OFF_BH + doff, Bhp + (size_t)row * K   + k0 + lc);
            cpasync16(base + OFF_BL + doff, Blp + (size_t)row * K   + k0 + lc);
        }
    };

    // per-lane ldmatrix offsets
    const uint32_t aoff = (uint32_t)(((wm * 64 + (lane & 15)) * RS + (lane >> 4) * 8) * 2);
    const uint32_t boff = (uint32_t)(((wn * 32 + (lane & 15)) * RS + (lane >> 4) * 8) * 2);

    load_stage(0, 0);
    CP_COMMIT();

    for (int c = 0; c < nc; c++) {
        if (c + 1 < nc) {
            load_stage((c + 1) & 1, (c + 1) * 64);
            CP_COMMIT();
            CP_WAIT(1);
        } else {
            CP_WAIT(0);
        }
        __syncthreads();
        const uint32_t base = sb + (c & 1) * ST_SIZE;
#pragma unroll
        for (int kc = 0; kc < 64; kc += 16) {
            uint32_t a[4][4], bh[2][4], bl[2][4];
#pragma unroll
            for (int mt = 0; mt < 4; mt++)
                ldsm_x4(a[mt], base + OFF_A + aoff + mt * (16 * RS * 2) + kc * 2);
#pragma unroll
            for (int p = 0; p < 2; p++)
                ldsm_x4(bh[p], base + OFF_BH + boff + p * (16 * RS * 2) + kc * 2);
#pragma unroll
            for (int p = 0; p < 2; p++)
                ldsm_x4(bl[p], base + OFF_BL + boff + p * (16 * RS * 2) + kc * 2);
#pragma unroll
            for (int mt = 0; mt < 4; mt++)
#pragma unroll
                for (int q = 0; q < 4; q++) {
                    mma16816(acc[mt][q], a[mt], bh[q >> 1][q & 1], bh[q >> 1][(q & 1) + 2]);
                    mma16816(acc[mt][q], a[mt], bl[q >> 1][q & 1], bl[q >> 1][(q & 1) + 2]);
                }
        }
        __syncthreads();
    }

    // ---- epilogue ----
    const int gid = lane >> 2, tig = lane & 3;
#pragma unroll
    for (int mt = 0; mt < 4; mt++) {
#pragma unroll
        for (int q = 0; q < 4; q++) {
            const int m = m0 + wm * 64 + mt * 16 + gid;
            const int n = nb + wn * 32 + q * 8 + tig * 2;
            const float* bp = bias + (size_t)v * biasV + n;
            const float b0 = bp[0], b1 = bp[1];
            float x0 = acc[mt][q][0] + b0, x1 = acc[mt][q][1] + b1;
            float y0 = acc[mt][q][2] + b0, y1 = acc[mt][q][3] + b1;
            if (mode == 1) {
                x0 = (x0 > 0.f) ? x0 : expm1f(x0);
                x1 = (x1 > 0.f) ? x1 : expm1f(x1);
                y0 = (y0 > 0.f) ? y0 : expm1f(y0);
                y1 = (y1 > 0.f) ? y1 : expm1f(y1);
            }
            if (mode == 0) {
                float* d0 = CF + (size_t)v * cV + (size_t)m * ldc + n;
                float2 o0; o0.x = x0; o0.y = x1;
                float2 o1; o1.x = y0; o1.y = y1;
                *reinterpret_cast<float2*>(d0) = o0;
                *reinterpret_cast<float2*>(d0 + 8 * ldc) = o1;
            } else {
                __half* d0 = CH + (size_t)v * cV + (size_t)m * ldc + n;
                *reinterpret_cast<__half2*>(d0) = __floats2half2_rn(x0, x1);
                *reinterpret_cast<__half2*>(d0 + 8 * ldc) = __floats2half2_rn(y0, y1);
            }
        }
    }
}

// ---------------------------------------------------------------------------
// skip = flat @ Wgs + bgs (N=16, SIMT)
// ---------------------------------------------------------------------------
__global__ __launch_bounds__(256)
void skip_kernel(const float* __restrict__ vars, const float* __restrict__ Wgs,
                 const float* __restrict__ bgs, float* __restrict__ skipOut)
{
    __shared__ float As[16][64];
    __shared__ float Ws[64][16];
    const int tid = threadIdx.x;
    const long t0 = (long)blockIdx.x * 16;
    const int o = tid & 15;
    const int tr = tid >> 4;
    const int awr = tid >> 4;
    const int awc = (tid & 15) << 2;
    const int wwr = tid >> 2;
    const int wwc = (tid & 3) << 2;
    float s = 0.f;
    for (int k0 = 0; k0 < DIN; k0 += 64) {
        float4 av = *reinterpret_cast<const float4*>(vars + (t0 + awr) * DIN + k0 + awc);
        *reinterpret_cast<float4*>(&As[awr][awc]) = av;
        float4 wv = *reinterpret_cast<const float4*>(Wgs + (long)(k0 + wwr) * 16 + wwc);
        *reinterpret_cast<float4*>(&Ws[wwr][wwc]) = wv;
        __syncthreads();
#pragma unroll 16
        for (int kk = 0; kk < 64; kk++) s += As[tr][kk] * Ws[kk][o];
        __syncthreads();
    }
    skipOut[(t0 + tr) * 16 + o] = s + bgs[o];
}

// ---------------------------------------------------------------------------
// weight logits -> softmax weights (one warp per token)
// ---------------------------------------------------------------------------
__global__ __launch_bounds__(256)
void wlogits_kernel(const float* __restrict__ h2, const float* __restrict__ Wg3,
                    const float* __restrict__ bg3, const float* __restrict__ gg,
                    const float* __restrict__ bgn, const float* __restrict__ skipIn,
                    float* __restrict__ wout)
{
    const int tid = threadIdx.x;
    const int lane = tid & 31;
    const long t = (long)blockIdx.x * 8 + (tid >> 5);
    const float* h2t = h2 + t * 256;
    float s = bg3[lane];
    for (int k = 0; k < 256; k++) s += h2t[k] * Wg3[k * 32 + lane];
    float bhalf = __shfl_down_sync(0xffffffffu, s, 16);
    float r = 0.f;
    if (lane < 16)
        r = s * (1.f / (1.f + expf(-bhalf))) + skipIn[t * 16 + lane];
    float sum = r;
    for (int m = 8; m; m >>= 1) sum += __shfl_xor_sync(0xffffffffu, sum, m, 16);
    float mean = sum * (1.f / 16.f);
    float d = r - mean;
    float vs = d * d;
    for (int m = 8; m; m >>= 1) vs += __shfl_xor_sync(0xffffffffu, vs, m, 16);
    float rstd = rsqrtf(vs * (1.f / 16.f) + 1e-6f);
    float ln = 0.f;
    if (lane < 16) ln = d * rstd * gg[lane] + bgn[lane];
    float mx = ln;
    for (int m = 8; m; m >>= 1) mx = fmaxf(mx, __shfl_xor_sync(0xffffffffu, mx, m, 16));
    float e = (lane < 16) ? expf(ln - mx) : 0.f;
    float se = e;
    for (int m = 8; m; m >>= 1) se += __shfl_xor_sync(0xffffffffu, se, m, 16);
    if (lane < 16) wout[t * 16 + lane] = e / se;
}

// ---------------------------------------------------------------------------
// enc = LN(glu(hv3)+x) ; out = sum_v enc * weight[v]
// ---------------------------------------------------------------------------
__global__ __launch_bounds__(256)
void enc_combine_kernel(const float* __restrict__ vars, const float* __restrict__ hv3,
                        const float* __restrict__ wout, const float* __restrict__ gv,
                        const float* __restrict__ bvn, float* __restrict__ outp)
{
    const long t = blockIdx.x;
    const int tid = threadIdx.x;
    const int lane = tid & 31, wid = tid >> 5;
    __shared__ float sw[16];
    __shared__ float red[18];
    if (tid < 16) sw[tid] = wout[t * 16 + tid];
    __syncthreads();
    float acc = 0.f;
    for (int v = 0; v < 16; v++) {
        size_t base = ((size_t)v * BT_TOK + t) * 512;
        float a = hv3[base + tid];
        float b = hv3[base + 256 + tid];
        float x = vars[t * DIN + v * DDIM + tid];
        float e = a * (1.f / (1.f + expf(-b))) + x;
        float s1 = e, s2 = e * e;
        for (int m = 16; m; m >>= 1) {
            s1 += __shfl_xor_sync(0xffffffffu, s1, m);
            s2 += __shfl_xor_sync(0xffffffffu, s2, m);
        }
        if (lane == 0) { red[wid] = s1; red[8 + wid] = s2; }
        __syncthreads();
        if (tid == 0) {
            float t1 = 0.f, t2 = 0.f;
            for (int i = 0; i < 8; i++) { t1 += red[i]; t2 += red[8 + i]; }
            float mean = t1 * (1.f / 256.f);
            float var = t2 * (1.f / 256.f) - mean * mean;
            red[16] = mean;
            red[17] = rsqrtf(var + 1e-6f);
        }
        __syncthreads();
        float mean = red[16], rstd = red[17];
        float encv = (e - mean) * rstd * gv[v * DDIM + tid] + bvn[v * DDIM + tid];
        acc += encv * sw[v];
        __syncthreads();
    }
    outp[t * DDIM + tid] = acc;
}

// ---------------------------------------------------------------------------
extern "C" void kernel_launch(void* const* d_in, const int* in_sizes, int n_in,
                              void* d_out, int out_size)
{
    const float* vars = (const float*)d_in[0];
    const float* Wg1  = (const float*)d_in[1];
    const float* bg1  = (const float*)d_in[2];
    const float* Wg2  = (const float*)d_in[3];
    const float* bg2  = (const float*)d_in[4];
    const float* Wg3  = (const float*)d_in[5];
    const float* bg3  = (const float*)d_in[6];
    const float* Wgs  = (const float*)d_in[7];
    const float* bgs  = (const float*)d_in[8];
    const float* gg   = (const float*)d_in[9];
    const float* bgn  = (const float*)d_in[10];
    const float* Wv1  = (const float*)d_in[11];
    const float* bv1  = (const float*)d_in[12];
    const float* Wv2  = (const float*)d_in[13];
    const float* bv2  = (const float*)d_in[14];
    const float* Wv3  = (const float*)d_in[15];
    const float* bv3  = (const float*)d_in[16];
    const float* gv   = (const float*)d_in[17];
    const float* bvn  = (const float*)d_in[18];

    float* out  = (float*)d_out;
    float* wout = out + BT_TOK * DDIM;

    unsigned char* gb = nullptr;
    cudaGetSymbolAddress((void**)&gb, g_buf);
    __half* VH  = (__half*)(gb + O_VH);
    __half* H1  = (__half*)(gb + O_H1);
    float*  H2F = (float*)(gb + O_H2F);
    __half* V1  = (__half*)(gb + O_V1);
    __half* V2  = (__half*)(gb + O_V2);
    float*  V3F = (float*)(gb + O_V3F);
    float*  SKP = (float*)(gb + O_SKIP);
    __half* G1H = (__half*)(gb + O_G1H);
    __half* G1L = (__half*)(gb + O_G1L);
    __half* G2H = (__half*)(gb + O_G2H);
    __half* G2L = (__half*)(gb + O_G2L);
    __half* W1H = (__half*)(gb + O_W1H);
    __half* W1L = (__half*)(gb + O_W1L);
    __half* W2H = (__half*)(gb + O_W2H);
    __half* W2L = (__half*)(gb + O_W2L);
    __half* W3H = (__half*)(gb + O_W3H);
    __half* W3L = (__half*)(gb + O_W3L);

    cudaFuncSetAttribute(mma_gemm, cudaFuncAttributeMaxDynamicSharedMemorySize, SMEM_TOT);

    // conversions
    conv_split<<<65536, 256>>>(vars, VH);
    conv_wT<<<dim3(8, 128, 1), 256>>>(Wg1, G1H, G1L, 4096, 256);
    conv_wT<<<dim3(8, 8, 1),   256>>>(Wg2, G2H, G2L, 256, 256);
    conv_wT<<<dim3(8, 8, 16),  256>>>(Wv1, W1H, W1L, 256, 256);
    conv_wT<<<dim3(8, 8, 16),  256>>>(Wv2, W2H, W2L, 256, 256);
    conv_wT<<<dim3(16, 8, 16), 256>>>(Wv3, W3H, W3L, 256, 512);

    // skip path (fp32)
    skip_kernel<<<1024, 256>>>(vars, Wgs, bgs, SKP);

    const long long S1 = BT_TOK * 256;
    const long long S3 = BT_TOK * 512;

    // G1: h1 = elu(flat @ Wg1 + bg1)
    mma_gemm<<<dim3(2, 128, 1), 256, SMEM_TOT>>>(
        VH, 0, DIN, G1H, G1L, 0, bg1, 0,
        nullptr, H1, 0, 256, 4096, 1);
    // G2: h2 = h1 @ Wg2 + bg2 (fp32 out)
    mma_gemm<<<dim3(2, 128, 1), 256, SMEM_TOT>>>(
        H1, 0, 256, G2H, G2L, 0, bg2, 0,
        H2F, nullptr, 0, 256, 256, 0);
    wlogits_kernel<<<2048, 256>>>(H2F, Wg3, bg3, gg, bgn, SKP, wout);
    // G3: hv1 = elu(x_v @ Wv1[v] + bv1[v])
    mma_gemm<<<dim3(2, 128, 16), 256, SMEM_TOT>>>(
        VH, 256, DIN, W1H, W1L, 65536, bv1, 256,
        nullptr, V1, S1, 256, 256, 1);
    // G4: hv2 = hv1 @ Wv2[v] + bv2[v]
    mma_gemm<<<dim3(2, 128, 16), 256, SMEM_TOT>>>(
        V1, S1, 256, W2H, W2L, 65536, bv2, 256,
        nullptr, V2, S1, 256, 256, 2);
    // G5: hv3 = hv2 @ Wv3[v] + bv3[v]  (N=512, fp32 out)
    mma_gemm<<<dim3(4, 128, 16), 256, SMEM_TOT>>>(
        V2, S1, 256, W3H, W3L, (long long)512 * 256, bv3, 512,
        V3F, nullptr, S3, 512, 256, 0);
    // final combine
    enc_combine_kernel<<<16384, 256>>>(vars, V3F, wout, gv, bvn, out);
}

// round 4
// speedup vs baseline: 3.5494x; 1.3138x over previous
#include <cuda_runtime.h>
#include <cuda_fp16.h>
#include <cstdint>

// ---------------------------------------------------------------------------
// VSN on GB300 — Round 4: single-pass fp16 mma.sync GEMMs, 4-stage cp.async,
// fp16 intermediates everywhere, smem-staged wlogits.
// B=8,T=2048,NV=16,D=256 -> BT=16384, DIN=4096
// ---------------------------------------------------------------------------

#define BT_TOK 16384L
#define DDIM   256
#define DIN    4096

// ---------------- scratch (bytes) ----------------
#define O_VH    0ULL            // vars fp16 [16384,4096]          128MB
#define O_H1    134217728ULL    // h1 fp16 [16384,256]
#define O_H2F   142606336ULL    // h2 fp32 [16384,256]
#define O_V1    159383552ULL    // hv1 fp16 16x[16384,256]
#define O_V2    293601280ULL    // hv2 fp16 16x[16384,256]
#define O_V3H   427819008ULL    // hv3 fp16 16x[16384,512]         256MB
#define O_SKIP  696254464ULL    // skip fp32 [16384,16]
#define O_G1    697303040ULL    // Wg1^T fp16 [256,4096]
#define O_G2    699400192ULL    // Wg2^T fp16 [256,256]
#define O_W1    699531264ULL    // Wv1^T fp16 16x[256,256]
#define O_W2    701628416ULL
#define O_W3    703725568ULL    // Wv3^T fp16 16x[512,256]
#define G_TOTAL 707919872ULL

__device__ __align__(1024) unsigned char g_buf[G_TOTAL];

// ---------------- helpers ----------------
__device__ __forceinline__ uint32_t smem_u32(const void* p) {
    uint32_t a;
    asm("{ .reg .u64 t; cvta.to.shared.u64 t, %1; cvt.u32.u64 %0, t; }" : "=r"(a) : "l"(p));
    return a;
}
__device__ __forceinline__ void cpasync16(uint32_t dst, const void* src) {
    asm volatile("cp.async.cg.shared.global [%0], [%1], 16;" :: "r"(dst), "l"(src));
}
#define CP_COMMIT() asm volatile("cp.async.commit_group;" ::: "memory")
#define CP_WAIT(n)  asm volatile("cp.async.wait_group %0;" :: "n"(n) : "memory")

__device__ __forceinline__ void ldsm_x4(uint32_t (&r)[4], uint32_t addr) {
    asm volatile("ldmatrix.sync.aligned.m8n8.x4.shared.b16 {%0,%1,%2,%3}, [%4];"
        : "=r"(r[0]), "=r"(r[1]), "=r"(r[2]), "=r"(r[3]) : "r"(addr));
}
__device__ __forceinline__ void mma16816(float (&c)[4], const uint32_t (&a)[4],
                                         uint32_t b0, uint32_t b1) {
    asm volatile("mma.sync.aligned.m16n8k16.row.col.f32.f16.f16.f32 "
        "{%0,%1,%2,%3}, {%4,%5,%6,%7}, {%8,%9}, {%0,%1,%2,%3};"
        : "+f"(c[0]), "+f"(c[1]), "+f"(c[2]), "+f"(c[3])
        : "r"(a[0]), "r"(a[1]), "r"(a[2]), "r"(a[3]), "r"(b0), "r"(b1));
}

// ---------------------------------------------------------------------------
// conversions
// ---------------------------------------------------------------------------
__global__ __launch_bounds__(256)
void conv_split(const float* __restrict__ x, __half* __restrict__ h)
{
    size_t i = ((size_t)blockIdx.x * 256 + threadIdx.x) * 4;
    float4 v = *reinterpret_cast<const float4*>(x + i);
    *reinterpret_cast<__half2*>(h + i)     = __floats2half2_rn(v.x, v.y);
    *reinterpret_cast<__half2*>(h + i + 2) = __floats2half2_rn(v.z, v.w);
}

// transpose: W[K,N] -> WT[N,K] (fp16)
__global__ __launch_bounds__(256)
void conv_wT(const float* __restrict__ W, __half* __restrict__ TH, int K, int N)
{
    const size_t vb = (size_t)blockIdx.z * K * N;
    __shared__ float tile[32][33];
    const int k0 = blockIdx.y * 32, n0 = blockIdx.x * 32;
    const int tx = threadIdx.x & 31, ty = threadIdx.x >> 5;  // 32 x 8
#pragma unroll
    for (int i = 0; i < 4; i++)
        tile[ty + i * 8][tx] = W[vb + (size_t)(k0 + ty + i * 8) * N + n0 + tx];
    __syncthreads();
#pragma unroll
    for (int i = 0; i < 4; i++) {
        int n = ty + i * 8;
        TH[vb + (size_t)(n0 + n) * K + k0 + tx] = __float2half_rn(tile[tx][n]);
    }
}

// ---------------------------------------------------------------------------
// fp16 mma.sync GEMM: C[128,128] tile = A[128,K] @ B^T, B stored [N,K].
// 8 warps: 2(M) x 4(N); warp tile 64x32; BK=64; 4-stage cp.async ring.
// mode: 0 = fp32 out, 1 = ELU + fp16 out, 2 = fp16 out
// ---------------------------------------------------------------------------
#define RS 72                       // smem row stride (elements), 144 bytes
#define OFF_B  18432                // 128 * 72 * 2
#define ST_SIZE 36864
#define SMEM_TOT 147456             // 4 stages

__global__ __launch_bounds__(256, 1)
void mma_gemm(const __half* __restrict__ A, long long aV, int lda,
              const __half* __restrict__ BH, long long bV,
              const float* __restrict__ bias, int biasV,
              float* __restrict__ CF, __half* __restrict__ CH,
              long long cV, int ldc, int K, int mode)
{
    extern __shared__ __align__(1024) unsigned char sm[];
    const uint32_t sb = smem_u32(sm);
    const int tid = threadIdx.x;
    const int lane = tid & 31, wid = tid >> 5;
    const int wm = wid & 1, wn = wid >> 1;
    const int v = blockIdx.z;
    const int m0 = blockIdx.y * 128;
    const int nb = blockIdx.x * 128;

    const __half* Ap  = A  + (size_t)v * aV + (size_t)m0 * lda;
    const __half* Bhp = BH + (size_t)v * bV + (size_t)nb * K;

    const int lr = tid >> 3;            // 0..31 (+ t*32)
    const int lc = (tid & 7) * 8;

    float acc[4][4][4];
#pragma unroll
    for (int i = 0; i < 4; i++)
#pragma unroll
        for (int j = 0; j < 4; j++)
#pragma unroll
            for (int k = 0; k < 4; k++) acc[i][j][k] = 0.f;

    const int nc = K >> 6;

    auto load_stage = [&](int s, int k0) {
        const uint32_t base = sb + s * ST_SIZE;
#pragma unroll
        for (int t = 0; t < 4; t++) {
            const int row = lr + t * 32;
            const uint32_t doff = (uint32_t)(row * RS + lc) * 2;
            cpasync16(base + doff,         Ap  + (size_t)row * lda + k0 + lc);
            cpasync16(base + OFF_B + doff, Bhp + (size_t)row * K   + k0 + lc);
        }
    };

    const uint32_t aoff = (uint32_t)(((wm * 64 + (lane & 15)) * RS + (lane >> 4) * 8) * 2);
    const uint32_t boff = (uint32_t)(((wn * 32 + (lane & 15)) * RS + (lane >> 4) * 8) * 2);

    // prologue: 3 stages in flight
    load_stage(0, 0);          CP_COMMIT();
    if (nc > 1) load_stage(1, 64);  CP_COMMIT();
    if (nc > 2) load_stage(2, 128); CP_COMMIT();

    for (int c = 0; c < nc; c++) {
        CP_WAIT(2);
        __syncthreads();
        const uint32_t base = sb + (c & 3) * ST_SIZE;
#pragma unroll
        for (int kc = 0; kc < 64; kc += 16) {
            uint32_t a[4][4], bh[2][4];
#pragma unroll
            for (int mt = 0; mt < 4; mt++)
                ldsm_x4(a[mt], base + aoff + mt * (16 * RS * 2) + kc * 2);
#pragma unroll
            for (int p = 0; p < 2; p++)
                ldsm_x4(bh[p], base + OFF_B + boff + p * (16 * RS * 2) + kc * 2);
#pragma unroll
            for (int mt = 0; mt < 4; mt++)
#pragma unroll
                for (int q = 0; q < 4; q++)
                    mma16816(acc[mt][q], a[mt], bh[q >> 1][q & 1], bh[q >> 1][(q & 1) + 2]);
        }
        __syncthreads();
        if (c + 3 < nc) load_stage((c + 3) & 3, (c + 3) * 64);
        CP_COMMIT();   // always commit (possibly empty group) to keep count stable
    }

    // ---- epilogue ----
    const int gid = lane >> 2, tig = lane & 3;
#pragma unroll
    for (int mt = 0; mt < 4; mt++) {
#pragma unroll
        for (int q = 0; q < 4; q++) {
            const int m = m0 + wm * 64 + mt * 16 + gid;
            const int n = nb + wn * 32 + q * 8 + tig * 2;
            const float* bp = bias + (size_t)v * biasV + n;
            const float b0 = bp[0], b1 = bp[1];
            float x0 = acc[mt][q][0] + b0, x1 = acc[mt][q][1] + b1;
            float y0 = acc[mt][q][2] + b0, y1 = acc[mt][q][3] + b1;
            if (mode == 1) {
                x0 = (x0 > 0.f) ? x0 : expm1f(x0);
                x1 = (x1 > 0.f) ? x1 : expm1f(x1);
                y0 = (y0 > 0.f) ? y0 : expm1f(y0);
                y1 = (y1 > 0.f) ? y1 : expm1f(y1);
            }
            if (mode == 0) {
                float* d0 = CF + (size_t)v * cV + (size_t)m * ldc + n;
                float2 o0; o0.x = x0; o0.y = x1;
                float2 o1; o1.x = y0; o1.y = y1;
                *reinterpret_cast<float2*>(d0) = o0;
                *reinterpret_cast<float2*>(d0 + 8 * ldc) = o1;
            } else {
                __half* d0 = CH + (size_t)v * cV + (size_t)m * ldc + n;
                *reinterpret_cast<__half2*>(d0) = __floats2half2_rn(x0, x1);
                *reinterpret_cast<__half2*>(d0 + 8 * ldc) = __floats2half2_rn(y0, y1);
            }
        }
    }
}

// ---------------------------------------------------------------------------
// skip = flat @ Wgs + bgs (reads fp16 VH)
// ---------------------------------------------------------------------------
__global__ __launch_bounds__(256)
void skip_kernel(const __half* __restrict__ vh, const float* __restrict__ Wgs,
                 const float* __restrict__ bgs, float* __restrict__ skipOut)
{
    __shared__ __half As[16][64];
    __shared__ float Ws[64][16];
    const int tid = threadIdx.x;
    const long t0 = (long)blockIdx.x * 16;
    const int o = tid & 15;
    const int tr = tid >> 4;
    float s = 0.f;
    for (int k0 = 0; k0 < DIN; k0 += 64) {
        *reinterpret_cast<uint2*>(&As[tid >> 4][(tid & 15) * 4]) =
            *reinterpret_cast<const uint2*>(vh + (t0 + (tid >> 4)) * DIN + k0 + (tid & 15) * 4);
        *reinterpret_cast<float4*>(&Ws[tid >> 2][(tid & 3) * 4]) =
            *reinterpret_cast<const float4*>(Wgs + (long)(k0 + (tid >> 2)) * 16 + (tid & 3) * 4);
        __syncthreads();
#pragma unroll 16
        for (int kk = 0; kk < 64; kk++) s += __half2float(As[tr][kk]) * Ws[kk][o];
        __syncthreads();
    }
    skipOut[(t0 + tr) * 16 + o] = s + bgs[o];
}

// ---------------------------------------------------------------------------
// weight logits -> softmax weights (one warp per token, Wg3 staged in smem)
// ---------------------------------------------------------------------------
__global__ __launch_bounds__(256)
void wlogits_kernel(const float* __restrict__ h2, const float* __restrict__ Wg3,
                    const float* __restrict__ bg3, const float* __restrict__ gg,
                    const float* __restrict__ bgn, const float* __restrict__ skipIn,
                    float* __restrict__ wout)
{
    __shared__ float Ws[256 * 32];
    const int tid = threadIdx.x;
    const int lane = tid & 31;
#pragma unroll
    for (int i = 0; i < 32; i++) Ws[tid + i * 256] = Wg3[tid + i * 256];
    __syncthreads();

    const long t = (long)blockIdx.x * 8 + (tid >> 5);
    const float* h2t = h2 + t * 256;
    float s = bg3[lane];
#pragma unroll 8
    for (int k = 0; k < 256; k += 4) {
        float4 h = *reinterpret_cast<const float4*>(h2t + k);
        s += h.x * Ws[(k + 0) * 32 + lane];
        s += h.y * Ws[(k + 1) * 32 + lane];
        s += h.z * Ws[(k + 2) * 32 + lane];
        s += h.w * Ws[(k + 3) * 32 + lane];
    }
    float bhalf = __shfl_down_sync(0xffffffffu, s, 16);
    float r = 0.f;
    if (lane < 16)
        r = s * (1.f / (1.f + expf(-bhalf))) + skipIn[t * 16 + lane];
    float sum = r;
    for (int m = 8; m; m >>= 1) sum += __shfl_xor_sync(0xffffffffu, sum, m, 16);
    float mean = sum * (1.f / 16.f);
    float d = r - mean;
    float vs = d * d;
    for (int m = 8; m; m >>= 1) vs += __shfl_xor_sync(0xffffffffu, vs, m, 16);
    float rstd = rsqrtf(vs * (1.f / 16.f) + 1e-6f);
    float ln = 0.f;
    if (lane < 16) ln = d * rstd * gg[lane] + bgn[lane];
    float mx = ln;
    for (int m = 8; m; m >>= 1) mx = fmaxf(mx, __shfl_xor_sync(0xffffffffu, mx, m, 16));
    float e = (lane < 16) ? expf(ln - mx) : 0.f;
    float se = e;
    for (int m = 8; m; m >>= 1) se += __shfl_xor_sync(0xffffffffu, se, m, 16);
    if (lane < 16) wout[t * 16 + lane] = e / se;
}

// ---------------------------------------------------------------------------
// enc = LN(glu(hv3)+x) ; out = sum_v enc * weight[v]   (fp16 hv3/x inputs)
// ---------------------------------------------------------------------------
__global__ __launch_bounds__(256)
void enc_combine_kernel(const __half* __restrict__ vh, const __half* __restrict__ hv3,
                        const float* __restrict__ wout, const float* __restrict__ gv,
                        const float* __restrict__ bvn, float* __restrict__ outp)
{
    const long t = blockIdx.x;
    const int tid = threadIdx.x;
    const int lane = tid & 31, wid = tid >> 5;
    __shared__ float sw[16];
    __shared__ float red[18];
    if (tid < 16) sw[tid] = wout[t * 16 + tid];
    __syncthreads();
    float acc = 0.f;
    for (int v = 0; v < 16; v++) {
        size_t base = ((size_t)v * BT_TOK + t) * 512;
        float a = __half2float(hv3[base + tid]);
        float b = __half2float(hv3[base + 256 + tid]);
        float x = __half2float(vh[t * DIN + v * DDIM + tid]);
        float e = a * (1.f / (1.f + expf(-b))) + x;
        float s1 = e, s2 = e * e;
        for (int m = 16; m; m >>= 1) {
            s1 += __shfl_xor_sync(0xffffffffu, s1, m);
            s2 += __shfl_xor_sync(0xffffffffu, s2, m);
        }
        if (lane == 0) { red[wid] = s1; red[8 + wid] = s2; }
        __syncthreads();
        if (wid == 0 && lane < 8) {
            float t1 = red[lane], t2 = red[8 + lane];
#pragma unroll
            for (int m = 4; m; m >>= 1) {
                t1 += __shfl_xor_sync(0x000000ffu, t1, m, 8);
                t2 += __shfl_xor_sync(0x000000ffu, t2, m, 8);
            }
            if (lane == 0) {
                float mean = t1 * (1.f / 256.f);
                float var = t2 * (1.f / 256.f) - mean * mean;
                red[16] = mean;
                red[17] = rsqrtf(var + 1e-6f);
            }
        }
        __syncthreads();
        float mean = red[16], rstd = red[17];
        float encv = (e - mean) * rstd * gv[v * DDIM + tid] + bvn[v * DDIM + tid];
        acc += encv * sw[v];
        __syncthreads();
    }
    outp[t * DDIM + tid] = acc;
}

// ---------------------------------------------------------------------------
extern "C" void kernel_launch(void* const* d_in, const int* in_sizes, int n_in,
                              void* d_out, int out_size)
{
    const float* vars = (const float*)d_in[0];
    const float* Wg1  = (const float*)d_in[1];
    const float* bg1  = (const float*)d_in[2];
    const float* Wg2  = (const float*)d_in[3];
    const float* bg2  = (const float*)d_in[4];
    const float* Wg3  = (const float*)d_in[5];
    const float* bg3  = (const float*)d_in[6];
    const float* Wgs  = (const float*)d_in[7];
    const float* bgs  = (const float*)d_in[8];
    const float* gg   = (const float*)d_in[9];
    const float* bgn  = (const float*)d_in[10];
    const float* Wv1  = (const float*)d_in[11];
    const float* bv1  = (const float*)d_in[12];
    const float* Wv2  = (const float*)d_in[13];
    const float* bv2  = (const float*)d_in[14];
    const float* Wv3  = (const float*)d_in[15];
    const float* bv3  = (const float*)d_in[16];
    const float* gv   = (const float*)d_in[17];
    const float* bvn  = (const float*)d_in[18];

    float* out  = (float*)d_out;
    float* wout = out + BT_TOK * DDIM;

    unsigned char* gb = nullptr;
    cudaGetSymbolAddress((void**)&gb, g_buf);
    __half* VH  = (__half*)(gb + O_VH);
    __half* H1  = (__half*)(gb + O_H1);
    float*  H2F = (float*)(gb + O_H2F);
    __half* V1  = (__half*)(gb + O_V1);
    __half* V2  = (__half*)(gb + O_V2);
    __half* V3H = (__half*)(gb + O_V3H);
    float*  SKP = (float*)(gb + O_SKIP);
    __half* G1T = (__half*)(gb + O_G1);
    __half* G2T = (__half*)(gb + O_G2);
    __half* W1T = (__half*)(gb + O_W1);
    __half* W2T = (__half*)(gb + O_W2);
    __half* W3T = (__half*)(gb + O_W3);

    cudaFuncSetAttribute(mma_gemm, cudaFuncAttributeMaxDynamicSharedMemorySize, SMEM_TOT);

    // conversions
    conv_split<<<65536, 256>>>(vars, VH);
    conv_wT<<<dim3(8, 128, 1), 256>>>(Wg1, G1T, 4096, 256);
    conv_wT<<<dim3(8, 8, 1),   256>>>(Wg2, G2T, 256, 256);
    conv_wT<<<dim3(8, 8, 16),  256>>>(Wv1, W1T, 256, 256);
    conv_wT<<<dim3(8, 8, 16),  256>>>(Wv2, W2T, 256, 256);
    conv_wT<<<dim3(16, 8, 16), 256>>>(Wv3, W3T, 256, 512);

    // skip path
    skip_kernel<<<1024, 256>>>(VH, Wgs, bgs, SKP);

    const long long S1 = BT_TOK * 256;
    const long long S3 = BT_TOK * 512;

    // G1: h1 = elu(flat @ Wg1 + bg1)
    mma_gemm<<<dim3(2, 128, 1), 256, SMEM_TOT>>>(
        VH, 0, DIN, G1T, 0, bg1, 0, nullptr, H1, 0, 256, 4096, 1);
    // G2: h2 = h1 @ Wg2 + bg2 (fp32 out)
    mma_gemm<<<dim3(2, 128, 1), 256, SMEM_TOT>>>(
        H1, 0, 256, G2T, 0, bg2, 0, H2F, nullptr, 0, 256, 256, 0);
    wlogits_kernel<<<2048, 256>>>(H2F, Wg3, bg3, gg, bgn, SKP, wout);
    // G3: hv1 = elu(x_v @ Wv1[v] + bv1[v])
    mma_gemm<<<dim3(2, 128, 16), 256, SMEM_TOT>>>(
        VH, 256, DIN, W1T, 65536, bv1, 256, nullptr, V1, S1, 256, 256, 1);
    // G4: hv2 = hv1 @ Wv2[v] + bv2[v]
    mma_gemm<<<dim3(2, 128, 16), 256, SMEM_TOT>>>(
        V1, S1, 256, W2T, 65536, bv2, 256, nullptr, V2, S1, 256, 256, 2);
    // G5: hv3 = hv2 @ Wv3[v] + bv3[v]  (N=512, fp16 out)
    mma_gemm<<<dim3(4, 128, 16), 256, SMEM_TOT>>>(
        V2, S1, 256, W3T, (long long)512 * 256, bv3, 512,
        nullptr, V3H, S3, 512, 256, 2);
    // final combine
    enc_combine_kernel<<<16384, 256>>>(VH, V3H, wout, gv, bvn, out);
}